// round 3
// baseline (speedup 1.0000x reference)
#include <cuda_runtime.h>

// SpatialTransformer: 1-D bilinear warp along W.
//
// Fast path: when the per-pixel gather indices are the identity pair
// (ia = w, ib = w+1 — true for any disparity in [0,1), but verified at
// runtime, never assumed), process 4 pixels per thread with one LDG.128 +
// one LDG.32 + one STG.128. General scalar fallback otherwise (row-end
// group and any non-unit-offset disparity).
//
// Coefficients are channel-invariant: computed once per 4-pixel group,
// reused across 16 channels per block. Grid = (H, B, C/16) = 4096 blocks.

#define ST_B 4
#define ST_C 64
#define ST_H 256
#define ST_W 512

constexpr int THREADS    = 128;          // 4 pixels/thread covers W=512
constexpr int CH_PER_BLK = 16;

__global__ void __launch_bounds__(THREADS)
spatial_transformer_vec_kernel(const float* __restrict__ in,
                               const float* __restrict__ disp,
                               float* __restrict__ out)
{
    const int t  = threadIdx.x;
    const int h  = blockIdx.x;
    const int b  = blockIdx.y;
    const int c0 = blockIdx.z * CH_PER_BLK;
    const int w0 = 4 * t;

    // ---- per-group coefficients (channel-invariant) ----
    const float* drow = disp + (b * ST_H + h) * ST_W;
    float4 d4 = *(const float4*)(drow + w0);
    float dv[4] = {d4.x, d4.y, d4.z, d4.w};

    float wa[4], wb[4];
    int   ia[4], ib[4];
    bool  fast = true;

    #pragma unroll
    for (int j = 0; j < 4; ++j) {
        int   w  = w0 + j;
        float ry = (float)w + dv[j];
        float ra = floorf(ry);
        float fb = ry - ra;
        int   a  = (int)ra;
        int   bb = a + 1;
        int   ac = min(max(a,  0), ST_W - 1);
        int   bc = min(max(bb, 0), ST_W - 1);
        float sc = (ry < 0.0f || ry > (float)(ST_W - 1)) ? 0.0f : 1.0f;
        wa[j] = (1.0f - fb) * sc;
        wb[j] = fb * sc;
        ia[j] = ac;
        ib[j] = bc;
        fast  = fast && (ac == w) && (bc == w + 1);
    }

    constexpr int HW = ST_H * ST_W;
    const size_t  base = ((size_t)(b * ST_C + c0) * ST_H + h) * ST_W;
    const float* src = in  + base;
    float*       dst = out + base;

    if (fast) {
        // 1x LDG.128 + 1x LDG.32 + 1x STG.128 per channel
        #pragma unroll 4
        for (int c = 0; c < CH_PER_BLK; ++c) {
            const float* row = src + c * HW;
            float4 v  = *(const float4*)(row + w0);
            float  vn = __ldg(row + w0 + 4);   // in-bounds: fast => w0 <= 504
            float4 o;
            o.x = fmaf(wa[0], v.x, wb[0] * v.y);
            o.y = fmaf(wa[1], v.y, wb[1] * v.z);
            o.z = fmaf(wa[2], v.z, wb[2] * v.w);
            o.w = fmaf(wa[3], v.w, wb[3] * vn);
            *(float4*)(dst + c * HW + w0) = o;
        }
    } else {
        // general gather fallback (row-end group; any disparity pattern)
        #pragma unroll 4
        for (int c = 0; c < CH_PER_BLK; ++c) {
            const float* row = src + c * HW;
            float4 o;
            o.x = fmaf(wa[0], __ldg(row + ia[0]), wb[0] * __ldg(row + ib[0]));
            o.y = fmaf(wa[1], __ldg(row + ia[1]), wb[1] * __ldg(row + ib[1]));
            o.z = fmaf(wa[2], __ldg(row + ia[2]), wb[2] * __ldg(row + ib[2]));
            o.w = fmaf(wa[3], __ldg(row + ia[3]), wb[3] * __ldg(row + ib[3]));
            *(float4*)(dst + c * HW + w0) = o;
        }
    }
}

extern "C" void kernel_launch(void* const* d_in, const int* in_sizes, int n_in,
                              void* d_out, int out_size)
{
    const float* right_input = (const float*)d_in[0];
    const float* disparity   = (const float*)d_in[1];
    float*       out         = (float*)d_out;

    dim3 grid(ST_H, ST_B, ST_C / CH_PER_BLK);   // 256 x 4 x 4 = 4096 blocks
    spatial_transformer_vec_kernel<<<grid, THREADS>>>(right_input, disparity, out);
}

// round 4
// speedup vs baseline: 1.2367x; 1.2367x over previous
#include <cuda_runtime.h>

// SpatialTransformer: 1-D bilinear warp along W, flat mapping.
//
// One thread per 4-element output group over the full B*C*H*W tensor
// (8.4M threads). All dims are powers of two -> index math is shifts.
// Coefficients recomputed per (channel, group) — cheap, pipes are idle —
// in exchange for maximal thread-level parallelism (latency hiding).
//
// Fast path (runtime-verified, never assumed): gather indices are the
// identity pair (ia=w, ib=w+1), so the 4-group needs one LDG.128 + one
// LDG.32. Scalar-gather fallback covers row-end groups and any
// non-[0,1) disparity.

#define ST_B 4
#define ST_C 64
#define ST_H 256
#define ST_W 512

// groups of 4 along W: 128 per row; total = 4*64*256*128 = 8,388,608
constexpr int NGROUPS = ST_B * ST_C * ST_H * (ST_W / 4);
constexpr int THREADS = 256;

__global__ void __launch_bounds__(THREADS)
spatial_transformer_flat_kernel(const float* __restrict__ in,
                                const float* __restrict__ disp,
                                float* __restrict__ out)
{
    const int g = blockIdx.x * blockDim.x + threadIdx.x;   // group id

    // decompose (all power-of-two): g = (((b*C + c)*H + h)*128 + gw)
    const int gw = g & 127;            // w-group within row
    const int h  = (g >> 7) & 255;     // H = 256
    const int b  = g >> 21;            // groups per batch = 2^21
    const int w0 = gw << 2;

    // disparity for this (b,h,w0..w0+3)
    const float4 d4 = *(const float4*)(disp + ((((b << 8) | h) << 9) | w0));
    const float dv[4] = {d4.x, d4.y, d4.z, d4.w};

    float wa[4], wb[4];
    int   ia[4], ib[4];
    bool  fast = true;

    #pragma unroll
    for (int j = 0; j < 4; ++j) {
        int   w  = w0 + j;
        float ry = (float)w + dv[j];
        float ra = floorf(ry);
        float fb = ry - ra;
        int   a  = (int)ra;
        int   ac = min(max(a,     0), ST_W - 1);
        int   bc = min(max(a + 1, 0), ST_W - 1);
        float sc = (ry < 0.0f || ry > (float)(ST_W - 1)) ? 0.0f : 1.0f;
        wa[j] = (1.0f - fb) * sc;
        wb[j] = fb * sc;
        ia[j] = ac;
        ib[j] = bc;
        fast  = fast && (ac == w) && (bc == w + 1);
    }

    const int elem = g << 2;                 // output elements are contiguous
    const float* row = in + (elem - w0);     // start of this (b,c,h) row

    float4 o;
    if (fast) {
        float4 v  = *(const float4*)(row + w0);
        float  vn = __ldg(row + w0 + 4);     // in-bounds: fast => w0 <= 504
        o.x = fmaf(wa[0], v.x, wb[0] * v.y);
        o.y = fmaf(wa[1], v.y, wb[1] * v.z);
        o.z = fmaf(wa[2], v.z, wb[2] * v.w);
        o.w = fmaf(wa[3], v.w, wb[3] * vn);
    } else {
        o.x = fmaf(wa[0], __ldg(row + ia[0]), wb[0] * __ldg(row + ib[0]));
        o.y = fmaf(wa[1], __ldg(row + ia[1]), wb[1] * __ldg(row + ib[1]));
        o.z = fmaf(wa[2], __ldg(row + ia[2]), wb[2] * __ldg(row + ib[2]));
        o.w = fmaf(wa[3], __ldg(row + ia[3]), wb[3] * __ldg(row + ib[3]));
    }
    *(float4*)(out + elem) = o;
}

extern "C" void kernel_launch(void* const* d_in, const int* in_sizes, int n_in,
                              void* d_out, int out_size)
{
    const float* right_input = (const float*)d_in[0];
    const float* disparity   = (const float*)d_in[1];
    float*       out         = (float*)d_out;

    const int blocks = NGROUPS / THREADS;    // 32768
    spatial_transformer_flat_kernel<<<blocks, THREADS>>>(right_input, disparity, out);
}

// round 6
// speedup vs baseline: 1.3904x; 1.1243x over previous
#include <cuda_runtime.h>

// SpatialTransformer: 1-D bilinear warp along W.
//
// Flat mapping, 4 channels per thread (2.1M threads). Coefficients are
// channel-invariant: computed ONCE per thread, held as just fb[4] in the
// fast path. Fast path (runtime-verified, never assumed): floor(w+d)==w
// and the 4-group is interior, which implies ia=w, ib=w+1, in-bounds ->
// out = va + fb*(vb-va): one LDG.128 + one LDG.32 per channel row-group.
// General fallback recomputes the exact reference formula (clamps + oob
// zeroing) with ROW-RELATIVE indices (R5 bug: base already includes w0).

#define ST_B 4
#define ST_C 64
#define ST_H 256
#define ST_W 512

constexpr int HW      = ST_H * ST_W;        // 131072
constexpr int NC      = 4;                  // channels per thread
constexpr int THREADS = 256;
// thread id decompose: g = ((b*16 + cg)*256 + h)*128 + gw
constexpr int NTHREADS = ST_B * (ST_C / NC) * ST_H * (ST_W / 4);  // 2,097,152

__global__ void __launch_bounds__(THREADS)
spatial_transformer_c4_kernel(const float* __restrict__ in,
                              const float* __restrict__ disp,
                              float* __restrict__ out)
{
    const int g  = blockIdx.x * blockDim.x + threadIdx.x;
    const int gw = g & 127;            // w-group (lanes -> consecutive: coalesced)
    const int h  = (g >> 7) & 255;
    const int cg = (g >> 15) & 15;
    const int b  = g >> 19;
    const int w0 = gw << 2;

    // disparity for (b, h, w0..w0+3) — 2 MB array, L2-hot (16x reuse)
    const float4 d4 = *(const float4*)(disp + ((((b << 8) | h) << 9) | w0));
    const float dv[4] = {d4.x, d4.y, d4.z, d4.w};

    float fb[4];
    bool  fast = (gw <= 126);          // need w0+4 < W for the fast path
    #pragma unroll
    for (int j = 0; j < 4; ++j) {
        float wj = (float)(w0 + j);
        float ry = wj + dv[j];
        float ra = floorf(ry);
        fb[j] = ry - ra;
        fast  = fast && (ra == wj);    // identity pair + in-bounds
    }

    const int c0   = cg << 2;
    const size_t base = ((size_t)((((b << 6) | c0) << 8) | h) << 9) + w0;
    const float* row  = in  + base;    // points at w0 within the row
    float*       orow = out + base;

    if (fast) {
        float4 v[NC];
        float  vn[NC];
        #pragma unroll
        for (int i = 0; i < NC; ++i) {          // front-batched: MLP = 8
            v[i]  = *(const float4*)(row + i * HW);
            vn[i] = __ldg(row + i * HW + 4);
        }
        #pragma unroll
        for (int i = 0; i < NC; ++i) {
            float4 o;
            o.x = fmaf(fb[0], v[i].y - v[i].x, v[i].x);
            o.y = fmaf(fb[1], v[i].z - v[i].y, v[i].y);
            o.z = fmaf(fb[2], v[i].w - v[i].z, v[i].z);
            o.w = fmaf(fb[3], vn[i]  - v[i].w, v[i].w);
            *(float4*)(orow + i * HW) = o;
        }
    } else {
        // exact reference formula (clamped gather + oob zeroing)
        float wa[4], wb[4];
        int   ia[4], ib[4];
        #pragma unroll
        for (int j = 0; j < 4; ++j) {
            int   w  = w0 + j;
            float ry = (float)w + dv[j];
            float ra = floorf(ry);
            float f  = ry - ra;
            int   a  = (int)ra;
            ia[j] = min(max(a,     0), ST_W - 1);
            ib[j] = min(max(a + 1, 0), ST_W - 1);
            float sc = (ry < 0.0f || ry > (float)(ST_W - 1)) ? 0.0f : 1.0f;
            wa[j] = (1.0f - f) * sc;
            wb[j] = f * sc;
        }
        #pragma unroll
        for (int i = 0; i < NC; ++i) {
            const float* r = row + i * HW - w0;   // ROW START (indices are absolute w)
            float4 o;
            o.x = fmaf(wa[0], __ldg(r + ia[0]), wb[0] * __ldg(r + ib[0]));
            o.y = fmaf(wa[1], __ldg(r + ia[1]), wb[1] * __ldg(r + ib[1]));
            o.z = fmaf(wa[2], __ldg(r + ia[2]), wb[2] * __ldg(r + ib[2]));
            o.w = fmaf(wa[3], __ldg(r + ia[3]), wb[3] * __ldg(r + ib[3]));
            *(float4*)(orow + i * HW) = o;
        }
    }
}

extern "C" void kernel_launch(void* const* d_in, const int* in_sizes, int n_in,
                              void* d_out, int out_size)
{
    const float* right_input = (const float*)d_in[0];
    const float* disparity   = (const float*)d_in[1];
    float*       out         = (float*)d_out;

    const int blocks = NTHREADS / THREADS;   // 8192
    spatial_transformer_c4_kernel<<<blocks, THREADS>>>(right_input, disparity, out);
}

// round 7
// speedup vs baseline: 1.4163x; 1.0186x over previous
#include <cuda_runtime.h>

// SpatialTransformer: 1-D bilinear warp along W.
//
// R6 structure (proven: 32 regs, occ 81.6%): flat mapping, 4 channels per
// thread, coefficients computed once per thread (fb[4] only in fast path).
// Fast path (runtime-verified, never assumed): floor(w+d)==w and interior
// group -> lerp va + fb*(vb-va), one LDG.128 + one LDG.32 per channel.
// Fallback = exact reference formula with row-relative indexing.
//
// R7 change: cache-policy hints. Input and output are strictly streaming
// (touched exactly once) -> __ldcs / __stcs (evict-first) so they do not
// thrash L2; disparity (2 MB, reused 16x) keeps default caching and stays
// L2-resident. Goal: raise achieved HBM bandwidth from 72.8%.

#define ST_B 4
#define ST_C 64
#define ST_H 256
#define ST_W 512

constexpr int HW      = ST_H * ST_W;        // 131072
constexpr int NC      = 4;                  // channels per thread
constexpr int THREADS = 256;
constexpr int NTHREADS = ST_B * (ST_C / NC) * ST_H * (ST_W / 4);  // 2,097,152

__global__ void __launch_bounds__(THREADS)
spatial_transformer_c4s_kernel(const float* __restrict__ in,
                               const float* __restrict__ disp,
                               float* __restrict__ out)
{
    const int g  = blockIdx.x * blockDim.x + threadIdx.x;
    const int gw = g & 127;            // w-group (lanes -> consecutive: coalesced)
    const int h  = (g >> 7) & 255;
    const int cg = (g >> 15) & 15;
    const int b  = g >> 19;
    const int w0 = gw << 2;

    // disparity (b, h, w0..w0+3): 2 MB, reused 16x -> default (L2-cached)
    const float4 d4 = *(const float4*)(disp + ((((b << 8) | h) << 9) | w0));
    const float dv[4] = {d4.x, d4.y, d4.z, d4.w};

    float fb[4];
    bool  fast = (gw <= 126);          // need w0+4 < W for the fast path
    #pragma unroll
    for (int j = 0; j < 4; ++j) {
        float wj = (float)(w0 + j);
        float ry = wj + dv[j];
        float ra = floorf(ry);
        fb[j] = ry - ra;
        fast  = fast && (ra == wj);    // identity pair + in-bounds
    }

    const int c0   = cg << 2;
    const size_t base = ((size_t)((((b << 6) | c0) << 8) | h) << 9) + w0;
    const float* row  = in  + base;    // points at w0 within the row
    float*       orow = out + base;

    if (fast) {
        float4 v[NC];
        float  vn[NC];
        #pragma unroll
        for (int i = 0; i < NC; ++i) {          // front-batched: MLP = 8
            v[i]  = __ldcs((const float4*)(row + i * HW));   // streaming read
            vn[i] = __ldcs(row + i * HW + 4);
        }
        #pragma unroll
        for (int i = 0; i < NC; ++i) {
            float4 o;
            o.x = fmaf(fb[0], v[i].y - v[i].x, v[i].x);
            o.y = fmaf(fb[1], v[i].z - v[i].y, v[i].y);
            o.z = fmaf(fb[2], v[i].w - v[i].z, v[i].z);
            o.w = fmaf(fb[3], vn[i]  - v[i].w, v[i].w);
            __stcs((float4*)(orow + i * HW), o);             // streaming write
        }
    } else {
        // exact reference formula (clamped gather + oob zeroing)
        float wa[4], wb[4];
        int   ia[4], ib[4];
        #pragma unroll
        for (int j = 0; j < 4; ++j) {
            int   w  = w0 + j;
            float ry = (float)w + dv[j];
            float ra = floorf(ry);
            float f  = ry - ra;
            int   a  = (int)ra;
            ia[j] = min(max(a,     0), ST_W - 1);
            ib[j] = min(max(a + 1, 0), ST_W - 1);
            float sc = (ry < 0.0f || ry > (float)(ST_W - 1)) ? 0.0f : 1.0f;
            wa[j] = (1.0f - f) * sc;
            wb[j] = f * sc;
        }
        #pragma unroll
        for (int i = 0; i < NC; ++i) {
            const float* r = row + i * HW - w0;   // row start (absolute w indices)
            float4 o;
            o.x = fmaf(wa[0], __ldg(r + ia[0]), wb[0] * __ldg(r + ib[0]));
            o.y = fmaf(wa[1], __ldg(r + ia[1]), wb[1] * __ldg(r + ib[1]));
            o.z = fmaf(wa[2], __ldg(r + ia[2]), wb[2] * __ldg(r + ib[2]));
            o.w = fmaf(wa[3], __ldg(r + ia[3]), wb[3] * __ldg(r + ib[3]));
            __stcs((float4*)(orow + i * HW), o);
        }
    }
}

extern "C" void kernel_launch(void* const* d_in, const int* in_sizes, int n_in,
                              void* d_out, int out_size)
{
    const float* right_input = (const float*)d_in[0];
    const float* disparity   = (const float*)d_in[1];
    float*       out         = (float*)d_out;

    const int blocks = NTHREADS / THREADS;   // 8192
    spatial_transformer_c4s_kernel<<<blocks, THREADS>>>(right_input, disparity, out);
}